// round 5
// baseline (speedup 1.0000x reference)
#include <cuda_runtime.h>
#include <cuda_bf16.h>
#include <cstdint>
#include <math.h>

// Problem constants
#define BB 32768
#define KK 8192
#define DD 384
#define NSPLIT 4
#define JBLOCKS 256

constexpr float INV_T = 1.0f / 0.07f;

// Tiling: CTA tile 128x256, k-chunk 128; 8 warps as 2(M) x 4(N), warp tile 64x64
#define BM 128
#define BN 256
#define BKC 128
constexpr int A_UNITS = DD / 8;              // 48 16B-units per A row
constexpr int A_BYTES = BM * DD * 2;         // 98304 per stripe
constexpr int B_CHUNK = BN * BKC * 2;        // 65536 per chunk
constexpr int CTRL    = A_BYTES + 2 * B_CHUNK;  // 229376
constexpr int SMEM_TOTAL = CTRL + 128;          // 229504

// Unit: 8 n-tiles (2048 cols) of one 128-row stripe. 24 chunks.
//   bid < 1024 : GEMM1 (feat x cent),  stripe=bid>>2, split=bid&3
//   bid >= 1024: GEMM2 (cent x cent),  stripe=(bid-1024)>>2, split=(bid-1024)&3
#define NTILES 8
#define NCHUNK (NTILES * 3)
#define GRID   1280

// Pre-swizzled GMEM images (exact byte images of smem tiles)
__device__ uint4 g_featS[BB * DD * 2 / 16];
__device__ uint4 g_centA[KK * DD * 2 / 16];
__device__ uint4 g_centB[KK * DD * 2 / 16];
__device__ float g_rowmax[NSPLIT * BB];
__device__ int   g_rowarg[NSPLIT * BB];
__device__ float g_centpart[NSPLIT * KK];
__device__ float g_jpart[JBLOCKS];

// ---------------------------------------------------------------------------
__device__ __forceinline__ uint32_t smem_u32(const void* p) {
    return (uint32_t)__cvta_generic_to_shared(p);
}
__device__ __forceinline__ void mbar_init(uint32_t a, uint32_t c) {
    asm volatile("mbarrier.init.shared.b64 [%0], %1;" :: "r"(a), "r"(c) : "memory");
}
__device__ __forceinline__ void mbar_expect(uint32_t a, uint32_t bytes) {
    asm volatile("mbarrier.arrive.expect_tx.shared.b64 _, [%0], %1;"
                 :: "r"(a), "r"(bytes) : "memory");
}
__device__ __forceinline__ void bulk_g2s(uint32_t dst, const void* src,
                                         uint32_t bytes, uint32_t mb) {
    asm volatile(
        "cp.async.bulk.shared::cluster.global.mbarrier::complete_tx::bytes "
        "[%0], [%1], %2, [%3];"
        :: "r"(dst), "l"(src), "r"(bytes), "r"(mb) : "memory");
}
__device__ __forceinline__ void mbar_wait(uint32_t addr, uint32_t parity) {
    asm volatile(
        "{\n\t.reg .pred P;\n\t"
        "WL%=:\n\t"
        "mbarrier.try_wait.parity.acquire.cta.shared::cta.b64 P, [%0], %1, 0x989680;\n\t"
        "@P bra WD%=;\n\t"
        "bra WL%=;\n\t"
        "WD%=:\n\t}"
        :: "r"(addr), "r"(parity) : "memory");
}
__device__ __forceinline__ uint32_t atom_inc_acqrel(uint32_t addr) {
    uint32_t old;
    asm volatile("atom.add.acq_rel.cta.shared::cta.u32 %0, [%1], 1;"
                 : "=r"(old) : "r"(addr) : "memory");
    return old;
}
#define FENCE_ASYNC() asm volatile("fence.proxy.async.shared::cta;" ::: "memory")

__device__ __forceinline__ void ldsm4(uint32_t (&d)[4], uint32_t addr) {
    asm volatile("ldmatrix.sync.aligned.m8n8.x4.shared.b16 {%0,%1,%2,%3}, [%4];"
                 : "=r"(d[0]), "=r"(d[1]), "=r"(d[2]), "=r"(d[3]) : "r"(addr));
}

// ---------------------------------------------------------------------------
// Prep: features fp32 -> bf16 pre-swizzled stripe images.
// ---------------------------------------------------------------------------
__global__ void k_prep_feat(const float* __restrict__ feat) {
    const int NU = BB * A_UNITS;
    for (int idx = blockIdx.x * blockDim.x + threadIdx.x; idx < NU;
         idx += gridDim.x * blockDim.x) {
        int u = idx % A_UNITS;
        int r = (idx / A_UNITS) % BM;
        int s = idx / (A_UNITS * BM);
        const float4* src =
            (const float4*)(feat + (size_t)(s * BM + r) * DD + u * 8);
        float4 f0 = src[0], f1 = src[1];
        __nv_bfloat162 p0 = __floats2bfloat162_rn(f0.x, f0.y);
        __nv_bfloat162 p1 = __floats2bfloat162_rn(f0.z, f0.w);
        __nv_bfloat162 p2 = __floats2bfloat162_rn(f1.x, f1.y);
        __nv_bfloat162 p3 = __floats2bfloat162_rn(f1.z, f1.w);
        uint4 v;
        v.x = *(uint32_t*)&p0; v.y = *(uint32_t*)&p1;
        v.z = *(uint32_t*)&p2; v.w = *(uint32_t*)&p3;
        g_featS[s * (BM * A_UNITS) + r * A_UNITS + (u ^ (r & 7))] = v;
    }
}

// ---------------------------------------------------------------------------
// Prep: centroids normalize -> bf16 as A-stripe and B-chunk images.
// ---------------------------------------------------------------------------
__global__ void k_prep_cent(const float* __restrict__ cent) {
    __shared__ float red[4];
    int row = blockIdx.x, t = threadIdx.x;
    const float* src = cent + (size_t)row * DD;
    float v0 = src[t], v1 = src[t + 128], v2 = src[t + 256];
    float s = v0 * v0 + v1 * v1 + v2 * v2;
#pragma unroll
    for (int o = 16; o > 0; o >>= 1) s += __shfl_xor_sync(0xffffffffu, s, o);
    if ((t & 31) == 0) red[t >> 5] = s;
    __syncthreads();
    float inv = 1.0f / fmaxf(sqrtf(red[0] + red[1] + red[2] + red[3]), 1e-12f);

    int j = -1;
    if (t < 48) j = t;
    else if (t >= 64 && t < 112) j = t - 64;
    if (j >= 0) {
        const float4* sp = (const float4*)(src + j * 8);
        float4 f0 = sp[0], f1 = sp[1];
        __nv_bfloat162 p0 = __floats2bfloat162_rn(f0.x * inv, f0.y * inv);
        __nv_bfloat162 p1 = __floats2bfloat162_rn(f0.z * inv, f0.w * inv);
        __nv_bfloat162 p2 = __floats2bfloat162_rn(f1.x * inv, f1.y * inv);
        __nv_bfloat162 p3 = __floats2bfloat162_rn(f1.z * inv, f1.w * inv);
        uint4 v;
        v.x = *(uint32_t*)&p0; v.y = *(uint32_t*)&p1;
        v.z = *(uint32_t*)&p2; v.w = *(uint32_t*)&p3;
        if (t < 48) {
            int sA = row >> 7, r = row & 127;
            g_centA[sA * (BM * A_UNITS) + r * A_UNITS + (j ^ (r & 7))] = v;
        } else {
            int nt = row >> 8, rr = row & 255, kc = j >> 4, uu = j & 15;
            g_centB[(size_t)(nt * 3 + kc) * 4096 + rr * 16 + (uu ^ (rr & 7))] = v;
        }
    }
}

// ---------------------------------------------------------------------------
// Fused GEMM, 1280 uniform CTAs (both GEMMs x 4 K-splits) in one launch.
// full[slot] mbarriers gate B-chunk arrival (tx-count). Buffer reuse is gated
// by a per-chunk smem counter: each warp's lane0 atom.add.acq_rel after its
// last smem read of the chunk; the warp seeing old==7 (the LAST finisher)
// issues the refill bulk itself -> no warp ever blocks on production.
// ---------------------------------------------------------------------------
__global__ void __launch_bounds__(256, 1) gemm_all() {
    extern __shared__ char smem[];
    const int tid = threadIdx.x, lane = tid & 31, wid = tid >> 5;
    const int wm = wid >> 2, wn = wid & 3;
    const uint32_t sb = smem_u32(smem);
    const uint32_t mbA  = sb + CTRL;         // A full
    const uint32_t mbF  = sb + CTRL + 8;     // B full[2]
    const uint32_t cnt0 = sb + CTRL + 24;    // NCHUNK u32 counters

    const int bid = blockIdx.x;
    int epi, stripe, split;
    if (bid < 1024) { epi = 0; stripe = bid >> 2; split = bid & 3; }
    else { epi = 1; stripe = (bid - 1024) >> 2; split = (bid - 1024) & 3; }
    const int row0 = stripe * BM;
    const int col_begin = split * (KK / NSPLIT);
    const int nt0 = col_begin / BN;
    const uint4* Asrc = (epi == 0 ? g_featS : g_centA)
                      + (size_t)stripe * (BM * A_UNITS);

    if (tid == 0) {
        mbar_init(mbA, 1);
        mbar_init(mbF, 1);
        mbar_init(mbF + 8, 1);
    }
    for (int i = tid; i < NCHUNK; i += 256)
        *(uint32_t*)(smem + CTRL + 24 + i * 4) = 0u;
    __syncthreads();

    auto issueB = [&](int c) {
        int slot = c & 1;
        uint32_t mb = mbF + slot * 8;
        const uint4* src = g_centB + (size_t)((nt0 + c / 3) * 3 + c % 3) * 4096;
        mbar_expect(mb, B_CHUNK);
        bulk_g2s(sb + A_BYTES + slot * B_CHUNK, src, B_CHUNK, mb);
    };
    if (tid == 0) {
        mbar_expect(mbA, A_BYTES);
        bulk_g2s(sb, Asrc, A_BYTES, mbA);
        issueB(0);
        issueB(1);
    }

    float acc[4][8][4];
    float bestv[8];
    int   besti[8];
    float rsum[8];
#pragma unroll
    for (int s = 0; s < 8; ++s) {
        bestv[s] = __int_as_float(0xff800000);
        besti[s] = 0;
        rsum[s]  = 0.0f;
    }

    mbar_wait(mbA, 0);  // A stripe resident

    for (int c = 0; c < NCHUNK; ++c) {
        const int slot = c & 1, kc = c % 3, nt = c / 3;
        mbar_wait(mbF + slot * 8, (uint32_t)((c >> 1) & 1));
        const uint32_t bbase = sb + A_BYTES + slot * B_CHUNK;

        if (kc == 0) {
#pragma unroll
            for (int mf = 0; mf < 4; ++mf)
#pragma unroll
                for (int nf = 0; nf < 8; ++nf)
#pragma unroll
                    for (int q = 0; q < 4; ++q) acc[mf][nf][q] = 0.0f;
        }

#pragma unroll
        for (int ks = 0; ks < 8; ++ks) {
            uint32_t a[4][4], b[4][4];
#pragma unroll
            for (int mf = 0; mf < 4; ++mf) {
                int r = wm * 64 + mf * 16 + (lane & 15);
                int u = kc * 16 + ks * 2 + (lane >> 4);
                ldsm4(a[mf], sb + (uint32_t)(r * A_UNITS + (u ^ (r & 7))) * 16u);
            }
#pragma unroll
            for (int np = 0; np < 4; ++np) {
                int r = wn * 64 + np * 16 + (lane & 7) + ((lane >> 4) << 3);
                int u = ks * 2 + ((lane >> 3) & 1);
                ldsm4(b[np], bbase + (uint32_t)(r * 16 + (u ^ (r & 7))) * 16u);
            }
#pragma unroll
            for (int mf = 0; mf < 4; ++mf)
#pragma unroll
                for (int nf = 0; nf < 8; ++nf) {
                    int np = nf >> 1, h = nf & 1;
                    asm volatile(
                        "mma.sync.aligned.m16n8k16.row.col.f32.bf16.bf16.f32 "
                        "{%0,%1,%2,%3}, {%4,%5,%6,%7}, {%8,%9}, {%0,%1,%2,%3};\n"
                        : "+f"(acc[mf][nf][0]), "+f"(acc[mf][nf][1]),
                          "+f"(acc[mf][nf][2]), "+f"(acc[mf][nf][3])
                        : "r"(a[mf][0]), "r"(a[mf][1]), "r"(a[mf][2]), "r"(a[mf][3]),
                          "r"(b[np][h * 2]), "r"(b[np][h * 2 + 1]));
                }
        }

        // Release this chunk's buffer; LAST warp to finish issues the refill.
        uint32_t last = 0;
        if (lane == 0) {
            uint32_t old = atom_inc_acqrel(cnt0 + c * 4);
            last = (old == 7u);
        }
        if (__shfl_sync(0xffffffffu, last, 0) && c + 2 < NCHUNK) {
            if (lane == 0) {
                FENCE_ASYNC();
                issueB(c + 2);
            }
        }

        if (kc == 2) {
            int cbase = col_begin + nt * BN + wn * 64 + 2 * (lane & 3);
#pragma unroll
            for (int mf = 0; mf < 4; ++mf)
#pragma unroll
                for (int nf = 0; nf < 8; ++nf) {
                    int col = cbase + nf * 8;
                    int s0 = mf * 2, s1 = mf * 2 + 1;
                    if (epi == 0) {
                        float v0 = acc[mf][nf][0], v1 = acc[mf][nf][1];
                        float v2 = acc[mf][nf][2], v3 = acc[mf][nf][3];
                        if (v0 > bestv[s0]) { bestv[s0] = v0; besti[s0] = col; }
                        if (v1 > bestv[s0]) { bestv[s0] = v1; besti[s0] = col + 1; }
                        if (v2 > bestv[s1]) { bestv[s1] = v2; besti[s1] = col; }
                        if (v3 > bestv[s1]) { bestv[s1] = v3; besti[s1] = col + 1; }
                    } else {
                        rsum[s0] += __expf(acc[mf][nf][0] * INV_T)
                                  + __expf(acc[mf][nf][1] * INV_T);
                        rsum[s1] += __expf(acc[mf][nf][2] * INV_T)
                                  + __expf(acc[mf][nf][3] * INV_T);
                    }
                }
        }
    }

    __syncthreads();  // all warps done with smem tiles -> reuse for reduction
    float* sred = (float*)smem;           // [4][128]
    int*   sarg = (int*)(smem + 2048);    // [4][128]
#pragma unroll
    for (int s = 0; s < 8; ++s) {
        int row = wm * 64 + (s >> 1) * 16 + (lane >> 2) + (s & 1) * 8;
        if (epi == 0) {
            float v = bestv[s];
            int ii = besti[s];
#pragma unroll
            for (int o = 1; o <= 2; o <<= 1) {
                float ov = __shfl_xor_sync(0xffffffffu, v, o);
                int oi = __shfl_xor_sync(0xffffffffu, ii, o);
                if (ov > v || (ov == v && oi < ii)) { v = ov; ii = oi; }
            }
            if ((lane & 3) == 0) { sred[wn * 128 + row] = v; sarg[wn * 128 + row] = ii; }
        } else {
            float v = rsum[s];
            v += __shfl_xor_sync(0xffffffffu, v, 1);
            v += __shfl_xor_sync(0xffffffffu, v, 2);
            if ((lane & 3) == 0) sred[wn * 128 + row] = v;
        }
    }
    __syncthreads();
    if (tid < 128) {
        if (epi == 0) {
            float v = sred[tid]; int ii = sarg[tid];
#pragma unroll
            for (int w = 1; w < 4; ++w) {
                float ov = sred[w * 128 + tid]; int oi = sarg[w * 128 + tid];
                if (ov > v || (ov == v && oi < ii)) { v = ov; ii = oi; }
            }
            g_rowmax[split * BB + row0 + tid] = v;
            g_rowarg[split * BB + row0 + tid] = ii;
        } else {
            g_centpart[split * KK + row0 + tid] =
                sred[tid] + sred[128 + tid] + sred[256 + tid] + sred[384 + tid];
        }
    }
}

// ---------------------------------------------------------------------------
// Per-sample loss: merge K-split maxima (ascending col ranges, strict > keeps
// the lowest index on ties), add centroid sums, reduce.
// ---------------------------------------------------------------------------
__global__ void k_finalj() {
    __shared__ float red[4];
    int i = blockIdx.x * 128 + threadIdx.x;
    float m = g_rowmax[i];
    int a = g_rowarg[i];
#pragma unroll
    for (int s = 1; s < NSPLIT; ++s) {
        float ms = g_rowmax[s * BB + i];
        int as_ = g_rowarg[s * BB + i];
        if (ms > m) { m = ms; a = as_; }
    }
    float S = g_centpart[a] + g_centpart[KK + a]
            + g_centpart[2 * KK + a] + g_centpart[3 * KK + a];
    float mt = m * INV_T;
    float J = mt - logf(expf(mt) + S);
    float s = J;
#pragma unroll
    for (int o = 16; o > 0; o >>= 1) s += __shfl_xor_sync(0xffffffffu, s, o);
    if ((threadIdx.x & 31) == 0) red[threadIdx.x >> 5] = s;
    __syncthreads();
    if (threadIdx.x == 0) g_jpart[blockIdx.x] = red[0] + red[1] + red[2] + red[3];
}

__global__ void k_reduce(float* out) {
    __shared__ float red[8];
    int t = threadIdx.x; // 256
    float s = g_jpart[t];
#pragma unroll
    for (int o = 16; o > 0; o >>= 1) s += __shfl_xor_sync(0xffffffffu, s, o);
    if ((t & 31) == 0) red[t >> 5] = s;
    __syncthreads();
    if (t == 0) {
        float tot = 0.0f;
        for (int i = 0; i < 8; ++i) tot += red[i];
        out[0] = -tot / (float)BB;
    }
}

// ---------------------------------------------------------------------------
extern "C" void kernel_launch(void* const* d_in, const int* in_sizes, int n_in,
                              void* d_out, int out_size) {
    const float* feat = (const float*)d_in[0];
    const float* cent = (const float*)d_in[1];
    if (n_in >= 2 && in_sizes[0] == KK * DD && in_sizes[1] == BB * DD) {
        feat = (const float*)d_in[1];
        cent = (const float*)d_in[0];
    }

    cudaFuncSetAttribute((const void*)gemm_all,
                         cudaFuncAttributeMaxDynamicSharedMemorySize, SMEM_TOTAL);

    k_prep_feat<<<3072, 256>>>(feat);
    k_prep_cent<<<KK, 128>>>(cent);
    gemm_all<<<GRID, 256, SMEM_TOTAL>>>();
    k_finalj<<<JBLOCKS, 128>>>();
    k_reduce<<<1, 256>>>((float*)d_out);
}

// round 7
// speedup vs baseline: 1.2809x; 1.2809x over previous
#include <cuda_runtime.h>
#include <cuda_bf16.h>
#include <cstdint>
#include <math.h>

// Problem constants
#define BB 32768
#define KK 8192
#define DD 384
#define JBLOCKS 256

constexpr float INV_T = 1.0f / 0.07f;

// Tiling: CTA tile 128x256, k-chunk 128; 8 warps as 2(M) x 4(N), warp tile 64x64
#define BM 128
#define BN 256
#define BKC 128
constexpr int A_UNITS = DD / 8;              // 48 16B-units per A row
constexpr int A_BYTES = BM * DD * 2;         // 98304 per stripe
constexpr int B_CHUNK = BN * BKC * 2;        // 65536 per chunk
constexpr int CTRL    = A_BYTES + 2 * B_CHUNK;  // 229376
constexpr int SMEM_TOTAL = CTRL + 128;          // 229504

// Work units: 4 n-tiles (1024 cols) of one 128-row stripe = 12 chunks.
//   u < 2048 : GEMM1 (feat x cent): stripe=u>>3, seg=u&7
//   u >= 2048: GEMM2 (cent x cent): v=u-2048, stripe=v>>3, seg=v&7
// Output segments: oseg = seg*4 + wn  (32 disjoint column sets per row)
#define NTILES 4
#define NCHUNK 12
#define G1UNITS 2048
#define NUNITS  2560
#define OSEG    32

// Pre-swizzled GMEM images + outputs (device globals: no allocation allowed)
__device__ uint4 g_featS[BB * DD * 2 / 16];
__device__ uint4 g_centA[KK * DD * 2 / 16];
__device__ uint4 g_centB[KK * DD * 2 / 16];
__device__ float g_rowmax[OSEG * BB];
__device__ int   g_rowarg[OSEG * BB];
__device__ float g_centpart[OSEG * KK];
__device__ float g_jpart[JBLOCKS];
__device__ unsigned g_work;

// ---------------------------------------------------------------------------
__device__ __forceinline__ uint32_t smem_u32(const void* p) {
    return (uint32_t)__cvta_generic_to_shared(p);
}
__device__ __forceinline__ void mbar_init(uint32_t a, uint32_t c) {
    asm volatile("mbarrier.init.shared.b64 [%0], %1;" :: "r"(a), "r"(c) : "memory");
}
__device__ __forceinline__ void mbar_expect(uint32_t a, uint32_t bytes) {
    asm volatile("mbarrier.arrive.expect_tx.shared.b64 _, [%0], %1;"
                 :: "r"(a), "r"(bytes) : "memory");
}
__device__ __forceinline__ void bulk_g2s(uint32_t dst, const void* src,
                                         uint32_t bytes, uint32_t mb) {
    asm volatile(
        "cp.async.bulk.shared::cluster.global.mbarrier::complete_tx::bytes "
        "[%0], [%1], %2, [%3];"
        :: "r"(dst), "l"(src), "r"(bytes), "r"(mb) : "memory");
}
__device__ __forceinline__ void mbar_wait(uint32_t addr, uint32_t parity) {
    asm volatile(
        "{\n\t.reg .pred P;\n\t"
        "WL%=:\n\t"
        "mbarrier.try_wait.parity.acquire.cta.shared::cta.b64 P, [%0], %1, 0x989680;\n\t"
        "@P bra WD%=;\n\t"
        "bra WL%=;\n\t"
        "WD%=:\n\t}"
        :: "r"(addr), "r"(parity) : "memory");
}
__device__ __forceinline__ uint32_t atom_inc_acqrel(uint32_t addr) {
    uint32_t old;
    asm volatile("atom.add.acq_rel.cta.shared::cta.u32 %0, [%1], 1;"
                 : "=r"(old) : "r"(addr) : "memory");
    return old;
}
#define FENCE_ASYNC() asm volatile("fence.proxy.async.shared::cta;" ::: "memory")

__device__ __forceinline__ void ldsm4(uint32_t (&d)[4], uint32_t addr) {
    asm volatile("ldmatrix.sync.aligned.m8n8.x4.shared.b16 {%0,%1,%2,%3}, [%4];"
                 : "=r"(d[0]), "=r"(d[1]), "=r"(d[2]), "=r"(d[3]) : "r"(addr));
}

// ---------------------------------------------------------------------------
// Prep: features fp32 -> bf16 pre-swizzled stripe images. Also resets g_work.
// ---------------------------------------------------------------------------
__global__ void k_prep_feat(const float* __restrict__ feat) {
    if (blockIdx.x == 0 && threadIdx.x == 0) g_work = 0u;
    const int NU = BB * A_UNITS;
    for (int idx = blockIdx.x * blockDim.x + threadIdx.x; idx < NU;
         idx += gridDim.x * blockDim.x) {
        int u = idx % A_UNITS;
        int r = (idx / A_UNITS) % BM;
        int s = idx / (A_UNITS * BM);
        const float4* src =
            (const float4*)(feat + (size_t)(s * BM + r) * DD + u * 8);
        float4 f0 = src[0], f1 = src[1];
        __nv_bfloat162 p0 = __floats2bfloat162_rn(f0.x, f0.y);
        __nv_bfloat162 p1 = __floats2bfloat162_rn(f0.z, f0.w);
        __nv_bfloat162 p2 = __floats2bfloat162_rn(f1.x, f1.y);
        __nv_bfloat162 p3 = __floats2bfloat162_rn(f1.z, f1.w);
        uint4 v;
        v.x = *(uint32_t*)&p0; v.y = *(uint32_t*)&p1;
        v.z = *(uint32_t*)&p2; v.w = *(uint32_t*)&p3;
        g_featS[s * (BM * A_UNITS) + r * A_UNITS + (u ^ (r & 7))] = v;
    }
}

// ---------------------------------------------------------------------------
// Prep: centroids normalize -> bf16 as A-stripe and B-chunk images.
// ---------------------------------------------------------------------------
__global__ void k_prep_cent(const float* __restrict__ cent) {
    __shared__ float red[4];
    int row = blockIdx.x, t = threadIdx.x;
    const float* src = cent + (size_t)row * DD;
    float v0 = src[t], v1 = src[t + 128], v2 = src[t + 256];
    float s = v0 * v0 + v1 * v1 + v2 * v2;
#pragma unroll
    for (int o = 16; o > 0; o >>= 1) s += __shfl_xor_sync(0xffffffffu, s, o);
    if ((t & 31) == 0) red[t >> 5] = s;
    __syncthreads();
    float inv = 1.0f / fmaxf(sqrtf(red[0] + red[1] + red[2] + red[3]), 1e-12f);

    int j = -1;
    if (t < 48) j = t;
    else if (t >= 64 && t < 112) j = t - 64;
    if (j >= 0) {
        const float4* sp = (const float4*)(src + j * 8);
        float4 f0 = sp[0], f1 = sp[1];
        __nv_bfloat162 p0 = __floats2bfloat162_rn(f0.x * inv, f0.y * inv);
        __nv_bfloat162 p1 = __floats2bfloat162_rn(f0.z * inv, f0.w * inv);
        __nv_bfloat162 p2 = __floats2bfloat162_rn(f1.x * inv, f1.y * inv);
        __nv_bfloat162 p3 = __floats2bfloat162_rn(f1.z * inv, f1.w * inv);
        uint4 v;
        v.x = *(uint32_t*)&p0; v.y = *(uint32_t*)&p1;
        v.z = *(uint32_t*)&p2; v.w = *(uint32_t*)&p3;
        if (t < 48) {
            int sA = row >> 7, r = row & 127;
            g_centA[sA * (BM * A_UNITS) + r * A_UNITS + (j ^ (r & 7))] = v;
        } else {
            int nt = row >> 8, rr = row & 255, kc = j >> 4, uu = j & 15;
            g_centB[(size_t)(nt * 3 + kc) * 4096 + rr * 16 + (uu ^ (rr & 7))] = v;
        }
    }
}

// ---------------------------------------------------------------------------
// Persistent fused GEMM: 152 CTAs, dynamic unit counter, pipeline never
// drains across units. Monotonic per-chunk counters (expected 8k+7) gate
// buffer reuse; the last finisher of chunk 9 grabs the next unit, finisher 10
// prefetches its B0, finisher 11 prefetches its A + B1 -- fills overlap the
// current unit's direct-to-global epilogue writeback.
// ---------------------------------------------------------------------------
__global__ void __launch_bounds__(256, 1) gemm_all() {
    extern __shared__ char smem[];
    const int tid = threadIdx.x, lane = tid & 31, wid = tid >> 5;
    const int wm = wid >> 2, wn = wid & 3;
    const uint32_t sb = smem_u32(smem);
    const uint32_t mbA = sb + CTRL;          // A full mbar
    const uint32_t mbF = sb + CTRL + 8;      // B full mbar[2]
    const uint32_t cnt = sb + CTRL + 24;     // 12 monotonic u32 counters
    uint32_t* const u_slot = (uint32_t*)(smem + CTRL + 72);

    auto issueA = [&](unsigned uu) {
        int isG1 = uu < G1UNITS;
        int stripe = (isG1 ? uu : uu - G1UNITS) >> 3;
        const uint4* src = (isG1 ? g_featS : g_centA)
                         + (size_t)stripe * (BM * A_UNITS);
        mbar_expect(mbA, A_BYTES);
        bulk_g2s(sb, src, A_BYTES, mbA);
    };
    auto issueB = [&](unsigned uu, int c) {
        int seg = (int)((uu < G1UNITS ? uu : uu - G1UNITS) & 7u);
        const uint4* src =
            g_centB + (size_t)((seg * NTILES + c / 3) * 3 + c % 3) * 4096;
        int slot = c & 1;
        mbar_expect(mbF + slot * 8, B_CHUNK);
        bulk_g2s(sb + A_BYTES + slot * B_CHUNK, src, B_CHUNK, mbF + slot * 8);
    };

    if (tid == 0) {
        mbar_init(mbA, 1);
        mbar_init(mbF, 1);
        mbar_init(mbF + 8, 1);
        *u_slot = atomicAdd(&g_work, 1u);
    }
    if (tid < NCHUNK) *(uint32_t*)(smem + CTRL + 24 + tid * 4) = 0u;
    __syncthreads();

    unsigned u = *u_slot;
    int k = 0;
    if (tid == 0 && u < NUNITS) {
        issueA(u);
        issueB(u, 0);
        issueB(u, 1);
    }

    while (u < NUNITS) {
        const int isG1 = u < G1UNITS;
        const int v_ = isG1 ? (int)u : (int)u - G1UNITS;
        const int stripe = v_ >> 3, seg = v_ & 7;
        const int row0 = stripe * BM;
        const int col_begin = seg * (NTILES * BN);

        float acc[4][8][4];
        float bestv[8];
        int   besti[8];
        float rsum[8];
#pragma unroll
        for (int s = 0; s < 8; ++s) {
            bestv[s] = __int_as_float(0xff800000);
            besti[s] = 0x7fffffff;
            rsum[s]  = 0.0f;
        }

        mbar_wait(mbA, (uint32_t)(k & 1));   // A stripe resident

        for (int c = 0; c < NCHUNK; ++c) {
            const int slot = c & 1, kc = c % 3, nt = c / 3;
            mbar_wait(mbF + slot * 8, (uint32_t)((c >> 1) & 1));
            const uint32_t bbase = sb + A_BYTES + slot * B_CHUNK;

            if (kc == 0) {
#pragma unroll
                for (int mf = 0; mf < 4; ++mf)
#pragma unroll
                    for (int nf = 0; nf < 8; ++nf)
#pragma unroll
                        for (int q = 0; q < 4; ++q) acc[mf][nf][q] = 0.0f;
            }

#pragma unroll
            for (int ks = 0; ks < 8; ++ks) {
                uint32_t a[4][4], b[4][4];
#pragma unroll
                for (int mf = 0; mf < 4; ++mf) {
                    int r = wm * 64 + mf * 16 + (lane & 15);
                    int uu = kc * 16 + ks * 2 + (lane >> 4);
                    ldsm4(a[mf],
                          sb + (uint32_t)(r * A_UNITS + (uu ^ (r & 7))) * 16u);
                }
#pragma unroll
                for (int np = 0; np < 4; ++np) {
                    int r = wn * 64 + np * 16 + (lane & 7) + ((lane >> 4) << 3);
                    int uu = ks * 2 + ((lane >> 3) & 1);
                    ldsm4(b[np],
                          bbase + (uint32_t)(r * 16 + (uu ^ (r & 7))) * 16u);
                }
#pragma unroll
                for (int mf = 0; mf < 4; ++mf)
#pragma unroll
                    for (int nf = 0; nf < 8; ++nf) {
                        int np = nf >> 1, h = nf & 1;
                        asm volatile(
                            "mma.sync.aligned.m16n8k16.row.col.f32.bf16.bf16.f32 "
                            "{%0,%1,%2,%3}, {%4,%5,%6,%7}, {%8,%9}, {%0,%1,%2,%3};\n"
                            : "+f"(acc[mf][nf][0]), "+f"(acc[mf][nf][1]),
                              "+f"(acc[mf][nf][2]), "+f"(acc[mf][nf][3])
                            : "r"(a[mf][0]), "r"(a[mf][1]), "r"(a[mf][2]),
                              "r"(a[mf][3]),
                              "r"(b[np][h * 2]), "r"(b[np][h * 2 + 1]));
                    }
            }

            // Buffer release + refill/prefetch by the LAST finisher of chunk c.
            if (lane == 0) {
                uint32_t old = atom_inc_acqrel(cnt + c * 4);
                if (old == (uint32_t)(8 * k + 7)) {
                    FENCE_ASYNC();
                    if (c <= NCHUNK - 3) issueB(u, c + 2);
                    if (c == NCHUNK - 3) {
                        *u_slot = atomicAdd(&g_work, 1u);  // grab next unit
                    } else if (c == NCHUNK - 2) {
                        unsigned un = *u_slot;             // via acq_rel chain
                        if (un < NUNITS) issueB(un, 0);
                    } else if (c == NCHUNK - 1) {
                        unsigned un = *u_slot;
                        if (un < NUNITS) { issueA(un); issueB(un, 1); }
                    }
                }
            }

            if (kc == 2) {
                int cbase = col_begin + nt * BN + wn * 64 + 2 * (lane & 3);
#pragma unroll
                for (int mf = 0; mf < 4; ++mf)
#pragma unroll
                    for (int nf = 0; nf < 8; ++nf) {
                        int col = cbase + nf * 8;
                        int s0 = mf * 2, s1 = mf * 2 + 1;
                        if (isG1) {
                            float v0 = acc[mf][nf][0], v1 = acc[mf][nf][1];
                            float v2 = acc[mf][nf][2], v3 = acc[mf][nf][3];
                            if (v0 > bestv[s0]) { bestv[s0] = v0; besti[s0] = col; }
                            if (v1 > bestv[s0]) { bestv[s0] = v1; besti[s0] = col + 1; }
                            if (v2 > bestv[s1]) { bestv[s1] = v2; besti[s1] = col; }
                            if (v3 > bestv[s1]) { bestv[s1] = v3; besti[s1] = col + 1; }
                        } else {
                            rsum[s0] += __expf(acc[mf][nf][0] * INV_T)
                                      + __expf(acc[mf][nf][1] * INV_T);
                            rsum[s1] += __expf(acc[mf][nf][2] * INV_T)
                                      + __expf(acc[mf][nf][3] * INV_T);
                        }
                    }
            }
        }

        // Direct-to-global writeback (overlaps next unit's prefetch fills).
        const int oseg = seg * 4 + wn;
#pragma unroll
        for (int s = 0; s < 8; ++s) {
            int row = wm * 64 + (s >> 1) * 16 + (lane >> 2) + (s & 1) * 8;
            if (isG1) {
                float vv = bestv[s];
                int ii = besti[s];
#pragma unroll
                for (int o = 1; o <= 2; o <<= 1) {
                    float ov = __shfl_xor_sync(0xffffffffu, vv, o);
                    int oi = __shfl_xor_sync(0xffffffffu, ii, o);
                    if (ov > vv || (ov == vv && oi < ii)) { vv = ov; ii = oi; }
                }
                if ((lane & 3) == 0) {
                    g_rowmax[(size_t)oseg * BB + row0 + row] = vv;
                    g_rowarg[(size_t)oseg * BB + row0 + row] = ii;
                }
            } else {
                float vv = rsum[s];
                vv += __shfl_xor_sync(0xffffffffu, vv, 1);
                vv += __shfl_xor_sync(0xffffffffu, vv, 2);
                if ((lane & 3) == 0)
                    g_centpart[(size_t)oseg * KK + row0 + row] = vv;
            }
        }

        __syncthreads();   // broadcast u_slot; all warps aligned to next unit
        ++k;
        u = *u_slot;
    }
}

// ---------------------------------------------------------------------------
// Per-sample loss: merge 32 disjoint-segment candidates per row (first-max
// semantics via (>, ==&&idx<)), add 32 centroid partial sums, reduce.
// ---------------------------------------------------------------------------
__global__ void k_finalj() {
    __shared__ float red[4];
    int i = blockIdx.x * 128 + threadIdx.x;
    float m = __int_as_float(0xff800000);
    int a = 0x7fffffff;
#pragma unroll
    for (int o = 0; o < OSEG; ++o) {
        float ms = g_rowmax[(size_t)o * BB + i];
        int as_ = g_rowarg[(size_t)o * BB + i];
        if (ms > m || (ms == m && as_ < a)) { m = ms; a = as_; }
    }
    float S = 0.0f;
#pragma unroll
    for (int o = 0; o < OSEG; ++o) S += g_centpart[(size_t)o * KK + a];
    float mt = m * INV_T;
    float J = mt - logf(expf(mt) + S);
    float s = J;
#pragma unroll
    for (int o = 16; o > 0; o >>= 1) s += __shfl_xor_sync(0xffffffffu, s, o);
    if ((threadIdx.x & 31) == 0) red[threadIdx.x >> 5] = s;
    __syncthreads();
    if (threadIdx.x == 0) g_jpart[blockIdx.x] = red[0] + red[1] + red[2] + red[3];
}

__global__ void k_reduce(float* out) {
    __shared__ float red[8];
    int t = threadIdx.x; // 256
    float s = g_jpart[t];
#pragma unroll
    for (int o = 16; o > 0; o >>= 1) s += __shfl_xor_sync(0xffffffffu, s, o);
    if ((t & 31) == 0) red[t >> 5] = s;
    __syncthreads();
    if (t == 0) {
        float tot = 0.0f;
        for (int i = 0; i < 8; ++i) tot += red[i];
        out[0] = -tot / (float)BB;
    }
}

// ---------------------------------------------------------------------------
extern "C" void kernel_launch(void* const* d_in, const int* in_sizes, int n_in,
                              void* d_out, int out_size) {
    const float* feat = (const float*)d_in[0];
    const float* cent = (const float*)d_in[1];
    if (n_in >= 2 && in_sizes[0] == KK * DD && in_sizes[1] == BB * DD) {
        feat = (const float*)d_in[1];
        cent = (const float*)d_in[0];
    }

    cudaFuncSetAttribute((const void*)gemm_all,
                         cudaFuncAttributeMaxDynamicSharedMemorySize, SMEM_TOTAL);

    k_prep_feat<<<3072, 256>>>(feat);
    k_prep_cent<<<KK, 128>>>(cent);
    gemm_all<<<152, 256, SMEM_TOTAL>>>();
    k_finalj<<<JBLOCKS, 128>>>();
    k_reduce<<<1, 256>>>((float*)d_out);
}